// round 12
// baseline (speedup 1.0000x reference)
#include <cuda_runtime.h>
#include <cstdint>

#define BB 64
#define TT 1024
#define KK 256
#define HALF 128
#define SROWS 224          // transT rows cached in backtrace SMEM (224 KB)

// ---------------- scratch ---------------------------------------------------
__device__ float g_state[TT * BB * KK];    // all forward states, 64 MB
__device__ float g_transT[KK * KK];        // transposed transitions

// ---------------- helpers ---------------------------------------------------
__device__ __forceinline__ uint32_t smem_u32(const void* p) {
    return (uint32_t)__cvta_generic_to_shared(p);
}

// monotone float->u32 map: preserves ordering exactly (finite values)
__device__ __forceinline__ unsigned fmono(float f) {
    int b = __float_as_int(f);
    return (unsigned)(b ^ ((b >> 31) | 0x80000000));
}

__device__ __forceinline__ void cluster_sync_all() {
    asm volatile("barrier.cluster.arrive.aligned;" ::: "memory");
    asm volatile("barrier.cluster.wait.aligned;" ::: "memory");
}

__device__ __forceinline__ uint32_t mapa_peer(uint32_t laddr, unsigned peer) {
    uint32_t raddr;
    asm volatile("mapa.shared::cluster.u32 %0, %1, %2;"
                 : "=r"(raddr) : "r"(laddr), "r"(peer));
    return raddr;
}

__device__ __forceinline__ void mbar_init(uint32_t addr, unsigned count) {
    asm volatile("mbarrier.init.shared.b64 [%0], %1;" :: "r"(addr), "r"(count) : "memory");
}
// local arrive(1) + expect 'bytes' of incoming async-store traffic this phase
__device__ __forceinline__ void mbar_arrive_expect_tx(uint32_t addr, unsigned bytes) {
    asm volatile("mbarrier.arrive.expect_tx.shared.b64 _, [%0], %1;"
                 :: "r"(addr), "r"(bytes) : "memory");
}
__device__ __forceinline__ void mbar_wait_cluster(uint32_t addr, unsigned parity) {
    asm volatile(
        "{\n\t"
        ".reg .pred P1;\n\t"
        "WAIT_%=:\n\t"
        "mbarrier.try_wait.parity.acquire.cluster.shared::cta.b64 P1, [%0], %1, 0x989680;\n\t"
        "@P1 bra.uni DONE_%=;\n\t"
        "bra.uni WAIT_%=;\n\t"
        "DONE_%=:\n\t"
        "}"
        :: "r"(addr), "r"(parity) : "memory");
}
// one-way async store to cluster SMEM; counts 8 bytes on the given mbarrier
// (mbarrier must live in the same CTA as the destination address)
__device__ __forceinline__ void st_async_b64(uint32_t raddr, float2 v, uint32_t rmbar) {
    unsigned long long u;
    memcpy(&u, &v, 8);
    asm volatile(
        "st.async.weak.shared::cluster.mbarrier::complete_tx::bytes.b64 [%0], %1, [%2];"
        :: "r"(raddr), "l"(u), "r"(rmbar) : "memory");
}

// bit-exact add: rn(sv*1.0f + tr) == rn(sv + tr); FFMA-imm form runs at rt 1
__device__ __forceinline__ float addx(float sv, float tr) {
    return __fmaf_rn(sv, 1.0f, tr);
}

__global__ void noop_kernel() {}

// ---------------- transpose kernel ------------------------------------------
__global__ void transpose_kernel(const float* __restrict__ trans)
{
    __shared__ float tile[32][33];
    int bx = blockIdx.x, by = blockIdx.y;
    int x = bx * 32 + threadIdx.x;
    #pragma unroll
    for (int r = 0; r < 4; ++r) {
        int y = by * 32 + threadIdx.y + r * 8;
        tile[threadIdx.y + r * 8][threadIdx.x] = trans[y * KK + x];
    }
    __syncthreads();
    int x2 = by * 32 + threadIdx.x;
    #pragma unroll
    for (int r = 0; r < 4; ++r) {
        int y2 = bx * 32 + threadIdx.y + r * 8;
        g_transT[y2 * KK + x2] = tile[threadIdx.x][threadIdx.y + r * 8];
    }
}

// tree-max of 16 sums addx(sv[k], tr[k].<comp>) — exact (max is associative)
#define TREE16(res, svv, trr, comp) do {                                   \
    float x0 = addx(svv[0],  trr[0].comp),  x1 = addx(svv[1],  trr[1].comp);  \
    float x2 = addx(svv[2],  trr[2].comp),  x3 = addx(svv[3],  trr[3].comp);  \
    float x4 = addx(svv[4],  trr[4].comp),  x5 = addx(svv[5],  trr[5].comp);  \
    float x6 = addx(svv[6],  trr[6].comp),  x7 = addx(svv[7],  trr[7].comp);  \
    float x8 = addx(svv[8],  trr[8].comp),  x9 = addx(svv[9],  trr[9].comp);  \
    float xa = addx(svv[10], trr[10].comp), xb = addx(svv[11], trr[11].comp); \
    float xc = addx(svv[12], trr[12].comp), xd = addx(svv[13], trr[13].comp); \
    float xe = addx(svv[14], trr[14].comp), xf = addx(svv[15], trr[15].comp); \
    x0 = fmaxf(x0, x8); x1 = fmaxf(x1, x9); x2 = fmaxf(x2, xa);               \
    x3 = fmaxf(x3, xb); x4 = fmaxf(x4, xc); x5 = fmaxf(x5, xd);               \
    x6 = fmaxf(x6, xe); x7 = fmaxf(x7, xf);                                   \
    x0 = fmaxf(x0, x4); x1 = fmaxf(x1, x5); x2 = fmaxf(x2, x6);               \
    x3 = fmaxf(x3, x7);                                                       \
    x0 = fmaxf(x0, x2); x1 = fmaxf(x1, x3);                                   \
    res = fmaxf(x0, x1);                                                      \
} while (0)

// ---------------- forward kernel (no CTA barrier, all-st.async) -------------
// 2-CTA cluster per batch. CTA rank owns j in [rank*128,+128).
// Warp w, lane = g*4 + q; thread covers j-quad jcol = rank*128+w*16+q*4 and
// i = k*8 + g. Trans in registers. BOTH state halves move via st.async with
// tx-counting mbarriers: mbL[buf] counts own-CTA writers' local pushes (512B),
// mbP[buf] counts the peer CTA's pushes (512B). Phase A waits mbL, phase B
// waits mbP. No __syncthreads in the loop: warps free-run, skew bounded by
// the data dependency itself.
__global__ void __cluster_dims__(2, 1, 1) __launch_bounds__(256, 1)
fwd_kernel(const float* __restrict__ em, const float* __restrict__ trans)
{
    __shared__ float st[2][KK];
    __shared__ __align__(8) unsigned long long mbar[4];  // L0,L1,P0,P1

    const int bid  = blockIdx.x;
    const int b    = bid >> 1;
    const unsigned rank = bid & 1;
    const unsigned peer = rank ^ 1u;
    const int tid  = threadIdx.x;
    const int w    = tid >> 5;
    const int lane = tid & 31;
    const int q    = lane & 3;
    const int g    = lane >> 2;
    const int jcol = rank * HALF + w * 16 + q * 4;

    const uint32_t aL0 = smem_u32(&mbar[0]);
    const uint32_t aL1 = smem_u32(&mbar[1]);
    const uint32_t aP0 = smem_u32(&mbar[2]);
    const uint32_t aP1 = smem_u32(&mbar[3]);
    if (tid == 0) {
        mbar_init(aL0, 1); mbar_init(aL1, 1);
        mbar_init(aP0, 1); mbar_init(aP1, 1);
    }

    // transition registers
    float4 trA[16], trB[16];
    #pragma unroll
    for (int k = 0; k < 16; ++k)
        trA[k] = *(const float4*)&trans[(rank * HALF + k * 8 + g) * KK + jcol];
    #pragma unroll
    for (int k = 0; k < 16; ++k)
        trB[k] = *(const float4*)&trans[(peer * HALF + k * 8 + g) * KK + jcol];

    // initial state = emissions[b,0,:] (both CTAs load full row locally)
    {
        float v = em[(b * TT) * KK + tid];
        st[0][tid] = v;
        if (rank == 0) g_state[b * KK + tid] = v;
    }
    __syncthreads();            // st[0] visible CTA-wide (plain stores)
    cluster_sync_all();         // peer mbar init complete before any st.async

    const bool writer = (lane < 4);
    const int jW = rank * HALF + w * 16 + lane * 4;   // writer's j-quad
    // local + peer destinations per buffer; peer's mbP armed on their side
    const uint32_t lD0 = smem_u32(&st[0][jW]);
    const uint32_t lD1 = smem_u32(&st[1][jW]);
    const uint32_t pD0 = mapa_peer(lD0, peer);
    const uint32_t pD1 = mapa_peer(lD1, peer);
    const uint32_t rP0 = mapa_peer(aP0, peer);
    const uint32_t rP1 = mapa_peer(aP1, peer);
    unsigned pL0 = 0, pL1 = 0, pP0 = 0, pP1 = 0;      // per-warp parities

    float4 emCur = make_float4(0.f, 0.f, 0.f, 0.f);
    if (writer)
        emCur = __ldg((const float4*)&em[((b * TT + 1) * KK) + jW]);

    for (int t = 1; t < TT; ++t) {
        const int nb = t & 1;            // buffer being written (state t)
        const int cb = nb ^ 1;           // buffer holding state t-1
        const float* cur = st[cb];

        // arm this step's incoming tx (local 512B, peer 512B); tid0's warp has
        // already consumed the previous phase of mbar[nb] at step t-1.
        if (tid == 0) {
            mbar_arrive_expect_tx(nb ? aL1 : aL0, 512u);
            mbar_arrive_expect_tx(nb ? aP1 : aP0, 512u);
        }

        // prefetch next step's emission
        float4 emNxt = make_float4(0.f, 0.f, 0.f, 0.f);
        if (writer && (t + 1 < TT))
            emNxt = __ldg((const float4*)&em[((b * TT + t + 1) * KK) + jW]);

        // ---- wait local half of state(t-1) (t==1: plain stores + barrier) --
        if (t >= 2) {
            if (cb) { mbar_wait_cluster(aL1, pL1); pL1 ^= 1u; }
            else    { mbar_wait_cluster(aL0, pL0); pL0 ^= 1u; }
        }

        // ---- phase A: own-half i (tree-max, depth ~5) ----
        float sv[16];
        #pragma unroll
        for (int k = 0; k < 16; ++k)
            sv[k] = cur[rank * HALF + k * 8 + g];
        float a0, a1, a2, a3;
        TREE16(a0, sv, trA, x);
        TREE16(a1, sv, trA, y);
        TREE16(a2, sv, trA, z);
        TREE16(a3, sv, trA, w);

        // ---- wait peer half of state(t-1) (in flight during phase A) ----
        if (t >= 2) {
            if (cb) { mbar_wait_cluster(aP1, pP1); pP1 ^= 1u; }
            else    { mbar_wait_cluster(aP0, pP0); pP0 ^= 1u; }
        }

        // ---- phase B: peer-half i ----
        float sw[16];
        #pragma unroll
        for (int k = 0; k < 16; ++k)
            sw[k] = cur[peer * HALF + k * 8 + g];
        float b0, b1, b2, b3;
        TREE16(b0, sw, trB, x);
        TREE16(b1, sw, trB, y);
        TREE16(b2, sw, trB, z);
        TREE16(b3, sw, trB, w);
        a0 = fmaxf(a0, b0); a1 = fmaxf(a1, b1);
        a2 = fmaxf(a2, b2); a3 = fmaxf(a3, b3);

        // butterfly max over the 8 i-groups (lane bits 2..4)
        #pragma unroll
        for (int off = 4; off <= 16; off <<= 1) {
            a0 = fmaxf(a0, __shfl_xor_sync(0xffffffffu, a0, off));
            a1 = fmaxf(a1, __shfl_xor_sync(0xffffffffu, a1, off));
            a2 = fmaxf(a2, __shfl_xor_sync(0xffffffffu, a2, off));
            a3 = fmaxf(a3, __shfl_xor_sync(0xffffffffu, a3, off));
        }

        if (writer) {
            float4 ns = make_float4(a0 + emCur.x, a1 + emCur.y,
                                    a2 + emCur.z, a3 + emCur.w);
            const uint32_t lD = nb ? lD1 : lD0;
            const uint32_t lM = nb ? aL1 : aL0;
            const uint32_t pd = nb ? pD1 : pD0;
            const uint32_t pm = nb ? rP1 : rP0;
            st_async_b64(lD,     make_float2(ns.x, ns.y), lM);   // local half
            st_async_b64(lD + 8, make_float2(ns.z, ns.w), lM);
            st_async_b64(pd,     make_float2(ns.x, ns.y), pm);   // peer half
            st_async_b64(pd + 8, make_float2(ns.z, ns.w), pm);
            *(float4*)&g_state[(t * BB + b) * KK + jW] = ns;     // backtrace
        }
        emCur = emNxt;
        // no __syncthreads: next phase A's mbL wait provides the ordering
    }

    // drain the final phases (t=1023 wrote buf 1) so no st.async targets our
    // SMEM after exit; every warp waits, then cluster-sync.
    mbar_wait_cluster(aL1, pL1);
    mbar_wait_cluster(aP1, pP1);
    cluster_sync_all();
}

// ---------------- backtrace: serial argmax recompute along decoded path -----
// One CTA per batch, one active warp. Chain loop UNROLLED x8 so the prefetch
// buffers are static registers (no local-memory spill). Per step exactly TWO
// warp collectives: redux.max (value) + redux.min (first index). Exact
// first-index tie-break: min over candidates lane*8+slot with u == gmax.
extern __shared__ float sT[];

__global__ void __launch_bounds__(256, 1) backtrace_kernel(float* __restrict__ out)
{
    const int b   = blockIdx.x;
    const int tid = threadIdx.x;

    for (int idx = tid; idx < SROWS * (KK / 4); idx += 256)
        ((float4*)sT)[idx] = ((const float4*)g_transT)[idx];
    __syncthreads();
    if (tid >= 32) return;
    const int lane = tid;
    const int base = lane * 8;
    const unsigned FULL = 0xffffffffu;
    const int BIG = 0x7fffffff;

    int cur;

    // ---- last tag: argmax over state row 1023 ----
    {
        const float4* rp = (const float4*)(g_state + (1023 * BB + b) * KK) + lane * 2;
        float4 sa = __ldg(rp), sb = __ldg(rp + 1);
        unsigned u0 = fmono(sa.x), u1 = fmono(sa.y), u2 = fmono(sa.z), u3 = fmono(sa.w);
        unsigned u4 = fmono(sb.x), u5 = fmono(sb.y), u6 = fmono(sb.z), u7 = fmono(sb.w);
        unsigned um = max(max(max(u0, u1), max(u2, u3)),
                          max(max(u4, u5), max(u6, u7)));
        unsigned gmax = __reduce_max_sync(FULL, um);
        int i0 = (u0 == gmax) ? base + 0 : BIG;
        int i1 = (u1 == gmax) ? base + 1 : BIG;
        int i2 = (u2 == gmax) ? base + 2 : BIG;
        int i3 = (u3 == gmax) ? base + 3 : BIG;
        int i4 = (u4 == gmax) ? base + 4 : BIG;
        int i5 = (u5 == gmax) ? base + 5 : BIG;
        int i6 = (u6 == gmax) ? base + 6 : BIG;
        int i7 = (u7 == gmax) ? base + 7 : BIG;
        int idx = min(min(min(i0, i1), min(i2, i3)),
                      min(min(i4, i5), min(i6, i7)));
        cur = __reduce_min_sync(FULL, idx);
        if (lane == 0) out[b * TT + (TT - 1)] = (float)cur;
    }

    // one chain step: state row (t-1) given in (sa, sb); updates cur, writes out
    auto argstep = [&](float4 sa, float4 sb, int t) {
        const float* trow = (cur < SROWS) ? (sT + cur * KK)
                                          : (g_transT + cur * KK);
        float4 t0 = *(const float4*)(trow + base);
        float4 t1 = *(const float4*)(trow + base + 4);
        unsigned u0 = fmono(sa.x + t0.x), u1 = fmono(sa.y + t0.y);
        unsigned u2 = fmono(sa.z + t0.z), u3 = fmono(sa.w + t0.w);
        unsigned u4 = fmono(sb.x + t1.x), u5 = fmono(sb.y + t1.y);
        unsigned u6 = fmono(sb.z + t1.z), u7 = fmono(sb.w + t1.w);
        unsigned um = max(max(max(u0, u1), max(u2, u3)),
                          max(max(u4, u5), max(u6, u7)));
        unsigned gmax = __reduce_max_sync(FULL, um);
        int i0 = (u0 == gmax) ? base + 0 : BIG;
        int i1 = (u1 == gmax) ? base + 1 : BIG;
        int i2 = (u2 == gmax) ? base + 2 : BIG;
        int i3 = (u3 == gmax) ? base + 3 : BIG;
        int i4 = (u4 == gmax) ? base + 4 : BIG;
        int i5 = (u5 == gmax) ? base + 5 : BIG;
        int i6 = (u6 == gmax) ? base + 6 : BIG;
        int i7 = (u7 == gmax) ? base + 7 : BIG;
        int idx = min(min(min(i0, i1), min(i2, i3)),
                      min(min(i4, i5), min(i6, i7)));
        cur = __reduce_min_sync(FULL, idx);
        if (lane == 0) out[b * TT + (t - 1)] = (float)cur;
    };

    // depth-8 register prefetch; slot d holds row (1022 - d) = (t-1) at t=1023-d
    float4 pfa[8], pfb[8];
    #pragma unroll
    for (int d = 0; d < 8; ++d) {
        const float4* rp = (const float4*)(g_state + ((1022 - d) * BB + b) * KK) + lane * 2;
        pfa[d] = __ldg(rp);
        pfb[d] = __ldg(rp + 1);
    }

    int t = 1023;
    while (t >= 8) {                 // full blocks: slots are compile-time
        #pragma unroll
        for (int uu = 0; uu < 8; ++uu) {
            float4 sa = pfa[uu], sb = pfb[uu];
            int nrow = t - 9;        // refill slot uu for use 8 iters from now
            if (nrow >= 0) {
                const float4* rp = (const float4*)(g_state + (nrow * BB + b) * KK) + lane * 2;
                pfa[uu] = __ldg(rp);
                pfb[uu] = __ldg(rp + 1);
            }
            argstep(sa, sb, t);
            --t;
        }
    }
    while (t >= 1) {                 // tail (<=7 iters): direct loads, no arrays
        const float4* rp = (const float4*)(g_state + ((t - 1) * BB + b) * KK) + lane * 2;
        float4 sa = __ldg(rp), sb = __ldg(rp + 1);
        argstep(sa, sb, t);
        --t;
    }
}

// ---------------- launch ----------------------------------------------------
extern "C" void kernel_launch(void* const* d_in, const int* in_sizes, int n_in,
                              void* d_out, int out_size)
{
    const float* em    = (const float*)d_in[0];  // [B, T, K] fp32
    const float* trans = (const float*)d_in[1];  // [K, K] fp32
    float* out = (float*)d_out;                  // [B, T] fp32

    const int bt_smem = SROWS * KK * (int)sizeof(float);   // 229376
    cudaFuncSetAttribute(backtrace_kernel,
                         cudaFuncAttributeMaxDynamicSharedMemorySize, bt_smem);

    transpose_kernel<<<dim3(8, 8), dim3(32, 8)>>>(trans);   // launch 1
    noop_kernel<<<1, 32>>>();                               // launch 2
    noop_kernel<<<1, 32>>>();                               // launch 3
    fwd_kernel<<<2 * BB, 256>>>(em, trans);                 // launch 4 <- ncu
    backtrace_kernel<<<BB, 256, bt_smem>>>(out);            // launch 5
}

// round 13
// speedup vs baseline: 1.0080x; 1.0080x over previous
#include <cuda_runtime.h>
#include <cstdint>

#define BB 64
#define TT 1024
#define KK 256
#define HALF 128
#define SROWS 224          // transT rows cached in backtrace SMEM (224 KB)

// ---------------- scratch ---------------------------------------------------
__device__ float g_state[TT * BB * KK];    // all forward states, 64 MB
__device__ float g_transT[KK * KK];        // transposed transitions

// ---------------- helpers ---------------------------------------------------
__device__ __forceinline__ uint32_t smem_u32(const void* p) {
    return (uint32_t)__cvta_generic_to_shared(p);
}

// monotone float->u32 map: preserves ordering exactly (finite values)
__device__ __forceinline__ unsigned fmono(float f) {
    int b = __float_as_int(f);
    return (unsigned)(b ^ ((b >> 31) | 0x80000000));
}

__device__ __forceinline__ void cluster_sync_all() {
    asm volatile("barrier.cluster.arrive.aligned;" ::: "memory");
    asm volatile("barrier.cluster.wait.aligned;" ::: "memory");
}

__device__ __forceinline__ uint32_t mapa_peer(uint32_t laddr, unsigned peer) {
    uint32_t raddr;
    asm volatile("mapa.shared::cluster.u32 %0, %1, %2;"
                 : "=r"(raddr) : "r"(laddr), "r"(peer));
    return raddr;
}

__device__ __forceinline__ void mbar_init(uint32_t addr, unsigned count) {
    asm volatile("mbarrier.init.shared.b64 [%0], %1;" :: "r"(addr), "r"(count) : "memory");
}
// local arrive(1) + expect 'bytes' of incoming async-store traffic this phase
__device__ __forceinline__ void mbar_arrive_expect_tx(uint32_t addr, unsigned bytes) {
    asm volatile("mbarrier.arrive.expect_tx.shared.b64 _, [%0], %1;"
                 :: "r"(addr), "r"(bytes) : "memory");
}
__device__ __forceinline__ void mbar_wait_cluster(uint32_t addr, unsigned parity) {
    asm volatile(
        "{\n\t"
        ".reg .pred P1;\n\t"
        "WAIT_%=:\n\t"
        "mbarrier.try_wait.parity.acquire.cluster.shared::cta.b64 P1, [%0], %1, 0x989680;\n\t"
        "@P1 bra.uni DONE_%=;\n\t"
        "bra.uni WAIT_%=;\n\t"
        "DONE_%=:\n\t"
        "}"
        :: "r"(addr), "r"(parity) : "memory");
}
// one-way async store to cluster SMEM; counts 8 bytes on the given mbarrier
// (mbarrier must live in the same CTA as the destination address)
__device__ __forceinline__ void st_async_b64(uint32_t raddr, float2 v, uint32_t rmbar) {
    unsigned long long u;
    memcpy(&u, &v, 8);
    asm volatile(
        "st.async.weak.shared::cluster.mbarrier::complete_tx::bytes.b64 [%0], %1, [%2];"
        :: "r"(raddr), "l"(u), "r"(rmbar) : "memory");
}

// bit-exact add: rn(sv*1.0f + tr) == rn(sv + tr); FFMA-imm form runs at rt 1
__device__ __forceinline__ float addx(float sv, float tr) {
    return __fmaf_rn(sv, 1.0f, tr);
}

__global__ void noop_kernel() {}

// ---------------- transpose kernel ------------------------------------------
__global__ void transpose_kernel(const float* __restrict__ trans)
{
    __shared__ float tile[32][33];
    int bx = blockIdx.x, by = blockIdx.y;
    int x = bx * 32 + threadIdx.x;
    #pragma unroll
    for (int r = 0; r < 4; ++r) {
        int y = by * 32 + threadIdx.y + r * 8;
        tile[threadIdx.y + r * 8][threadIdx.x] = trans[y * KK + x];
    }
    __syncthreads();
    int x2 = by * 32 + threadIdx.x;
    #pragma unroll
    for (int r = 0; r < 4; ++r) {
        int y2 = bx * 32 + threadIdx.y + r * 8;
        g_transT[y2 * KK + x2] = tile[threadIdx.x][threadIdx.y + r * 8];
    }
}

// quad max over 16 own-i values: two interleaved fmax chains per j, exact
// (max associative/commutative; addx bit-exact add)
#define QUADMAX(r0, r1, r2, r3, svv, trr) do {                              \
    float m0a = addx(svv[0], trr[0].x), m1a = addx(svv[0], trr[0].y);       \
    float m2a = addx(svv[0], trr[0].z), m3a = addx(svv[0], trr[0].w);       \
    float m0b = addx(svv[1], trr[1].x), m1b = addx(svv[1], trr[1].y);       \
    float m2b = addx(svv[1], trr[1].z), m3b = addx(svv[1], trr[1].w);       \
    _Pragma("unroll")                                                        \
    for (int kk = 2; kk < 16; kk += 2) {                                     \
        m0a = fmaxf(m0a, addx(svv[kk], trr[kk].x));                          \
        m1a = fmaxf(m1a, addx(svv[kk], trr[kk].y));                          \
        m2a = fmaxf(m2a, addx(svv[kk], trr[kk].z));                          \
        m3a = fmaxf(m3a, addx(svv[kk], trr[kk].w));                          \
        m0b = fmaxf(m0b, addx(svv[kk + 1], trr[kk + 1].x));                  \
        m1b = fmaxf(m1b, addx(svv[kk + 1], trr[kk + 1].y));                  \
        m2b = fmaxf(m2b, addx(svv[kk + 1], trr[kk + 1].z));                  \
        m3b = fmaxf(m3b, addx(svv[kk + 1], trr[kk + 1].w));                  \
    }                                                                        \
    r0 = fmaxf(m0a, m0b); r1 = fmaxf(m1a, m1b);                              \
    r2 = fmaxf(m2a, m2b); r3 = fmaxf(m3a, m3b);                              \
} while (0)

// ---------------- forward kernel (partial-max exchange) ---------------------
// 2-CTA cluster per batch. CTA rank owns j-half AND i-half [rank*128,+128):
// state for its i-half is always LOCAL (own j-half = own i-half next step).
// Per step each CTA computes partial maxes over its own 128 i for ALL 256 j:
//   phase P: peer's j-half partials -> st.async push to peer's recv buffer
//   phase O: own j-half partials    -> registers
//   wait peer's partials (flew during phase O), fmax + emission -> new state.
// State never crosses the cluster; only 512B of partials per CTA per step.
// recv mbarriers armed ONE STEP AHEAD so peer pushes always find them armed.
__global__ void __cluster_dims__(2, 1, 1) __launch_bounds__(256, 1)
fwd_kernel(const float* __restrict__ em, const float* __restrict__ trans)
{
    __shared__ float st[2][HALF];       // own-half state, double buffered
    __shared__ float recv[2][HALF];     // peer partials, double buffered
    __shared__ __align__(8) unsigned long long mbR[2];

    const int bid  = blockIdx.x;
    const int b    = bid >> 1;
    const unsigned rank = bid & 1;
    const unsigned peer = rank ^ 1u;
    const int tid  = threadIdx.x;
    const int w    = tid >> 5;
    const int lane = tid & 31;
    const int q    = lane & 3;
    const int g    = lane >> 2;

    const uint32_t aR0 = smem_u32(&mbR[0]);
    const uint32_t aR1 = aR0 + 8;
    if (tid == 0) {
        mbar_init(aR0, 1);
        mbar_init(aR1, 1);
        mbar_arrive_expect_tx(aR1, 512u);    // arm step 1 (buf 1) pre-cluster-sync
    }

    // transition registers: i = rank*128 + k*8 + g (own i-half)
    // trO: own j-quad  jO = rank*128 + w*16 + q*4
    // trP: peer j-quad jP = peer*128 + w*16 + q*4
    float4 trO[16], trP[16];
    #pragma unroll
    for (int k = 0; k < 16; ++k) {
        const float* row = &trans[(rank * HALF + k * 8 + g) * KK];
        trO[k] = *(const float4*)&row[rank * HALF + w * 16 + q * 4];
        trP[k] = *(const float4*)&row[peer * HALF + w * 16 + q * 4];
    }

    // initial state = emissions[b,0,own half]
    if (tid < HALF) {
        float v = em[(b * TT) * KK + rank * HALF + tid];
        st[0][tid] = v;
        g_state[b * KK + rank * HALF + tid] = v;
    }
    __syncthreads();
    cluster_sync_all();          // peer mbars init+armed before any st.async

    const bool writer = (lane < 4);
    const int jl = w * 16 + lane * 4;          // writer's local j-quad index
    const uint32_t rRecv0 = mapa_peer(smem_u32(&recv[0][jl]), peer);
    const uint32_t rRecv1 = mapa_peer(smem_u32(&recv[1][jl]), peer);
    const uint32_t rMb0 = mapa_peer(aR0, peer);
    const uint32_t rMb1 = mapa_peer(aR1, peer);
    unsigned pR0 = 0, pR1 = 0;

    float4 emCur = make_float4(0.f, 0.f, 0.f, 0.f);
    if (writer)
        emCur = __ldg((const float4*)&em[(b * TT + 1) * KK + rank * HALF + jl]);

    for (int t = 1; t < TT; ++t) {
        const int nb = t & 1;            // buffer for state t / recv of step t
        const int cb = nb ^ 1;

        // arm recv for step t+1 (buf cb) BEFORE this step's pushes: the peer's
        // step-(t+1) push cannot start until it gets our step-t push (below),
        // so the arm always precedes the traffic it counts.
        if (tid == 0 && (t + 1) < TT)
            mbar_arrive_expect_tx(nb ? aR0 : aR1, 512u);

        // prefetch next step's emission
        float4 emNxt = make_float4(0.f, 0.f, 0.f, 0.f);
        if (writer && (t + 1) < TT)
            emNxt = __ldg((const float4*)&em[(b * TT + t + 1) * KK + rank * HALF + jl]);

        // own-half state (local, visible via last step's __syncthreads)
        float sv[16];
        #pragma unroll
        for (int k = 0; k < 16; ++k)
            sv[k] = st[cb][k * 8 + g];

        // ---- phase P: partial maxes for PEER's j-half, push ASAP ----
        float p0, p1, p2, p3;
        QUADMAX(p0, p1, p2, p3, sv, trP);
        #pragma unroll
        for (int off = 4; off <= 16; off <<= 1) {
            p0 = fmaxf(p0, __shfl_xor_sync(0xffffffffu, p0, off));
            p1 = fmaxf(p1, __shfl_xor_sync(0xffffffffu, p1, off));
            p2 = fmaxf(p2, __shfl_xor_sync(0xffffffffu, p2, off));
            p3 = fmaxf(p3, __shfl_xor_sync(0xffffffffu, p3, off));
        }
        if (writer) {
            const uint32_t rd = nb ? rRecv1 : rRecv0;
            const uint32_t rm = nb ? rMb1 : rMb0;
            st_async_b64(rd,     make_float2(p0, p1), rm);
            st_async_b64(rd + 8, make_float2(p2, p3), rm);
        }

        // ---- phase O: partial maxes for OWN j-half (hides peer flight) ----
        float o0, o1, o2, o3;
        QUADMAX(o0, o1, o2, o3, sv, trO);
        #pragma unroll
        for (int off = 4; off <= 16; off <<= 1) {
            o0 = fmaxf(o0, __shfl_xor_sync(0xffffffffu, o0, off));
            o1 = fmaxf(o1, __shfl_xor_sync(0xffffffffu, o1, off));
            o2 = fmaxf(o2, __shfl_xor_sync(0xffffffffu, o2, off));
            o3 = fmaxf(o3, __shfl_xor_sync(0xffffffffu, o3, off));
        }

        // ---- wait peer partials (512B tx), assemble new state ----
        if (nb) { mbar_wait_cluster(aR1, pR1); pR1 ^= 1u; }
        else    { mbar_wait_cluster(aR0, pR0); pR0 ^= 1u; }

        if (writer) {
            float4 rv = *(const float4*)&recv[nb][jl];
            float4 ns = make_float4(fmaxf(o0, rv.x) + emCur.x,
                                    fmaxf(o1, rv.y) + emCur.y,
                                    fmaxf(o2, rv.z) + emCur.z,
                                    fmaxf(o3, rv.w) + emCur.w);
            *(float4*)&st[nb][jl] = ns;                                  // local
            *(float4*)&g_state[(t * BB + b) * KK + rank * HALF + jl] = ns;
        }
        emCur = emNxt;
        __syncthreads();   // st[nb] visible CTA-wide for next step's sv reads
    }

    cluster_sync_all();    // peer consumed all our pushes before SMEM dies
}

// ---------------- backtrace: serial argmax recompute along decoded path -----
// One CTA per batch, one active warp. Chain loop UNROLLED x8 so the prefetch
// buffers are static registers (no local-memory spill). Per step exactly TWO
// warp collectives: redux.max (value) + redux.min (first index). Exact
// first-index tie-break: min over candidates lane*8+slot with u == gmax.
extern __shared__ float sT[];

__global__ void __launch_bounds__(256, 1) backtrace_kernel(float* __restrict__ out)
{
    const int b   = blockIdx.x;
    const int tid = threadIdx.x;

    for (int idx = tid; idx < SROWS * (KK / 4); idx += 256)
        ((float4*)sT)[idx] = ((const float4*)g_transT)[idx];
    __syncthreads();
    if (tid >= 32) return;
    const int lane = tid;
    const int base = lane * 8;
    const unsigned FULL = 0xffffffffu;
    const int BIG = 0x7fffffff;

    int cur;

    // ---- last tag: argmax over state row 1023 ----
    {
        const float4* rp = (const float4*)(g_state + (1023 * BB + b) * KK) + lane * 2;
        float4 sa = __ldg(rp), sb = __ldg(rp + 1);
        unsigned u0 = fmono(sa.x), u1 = fmono(sa.y), u2 = fmono(sa.z), u3 = fmono(sa.w);
        unsigned u4 = fmono(sb.x), u5 = fmono(sb.y), u6 = fmono(sb.z), u7 = fmono(sb.w);
        unsigned um = max(max(max(u0, u1), max(u2, u3)),
                          max(max(u4, u5), max(u6, u7)));
        unsigned gmax = __reduce_max_sync(FULL, um);
        int i0 = (u0 == gmax) ? base + 0 : BIG;
        int i1 = (u1 == gmax) ? base + 1 : BIG;
        int i2 = (u2 == gmax) ? base + 2 : BIG;
        int i3 = (u3 == gmax) ? base + 3 : BIG;
        int i4 = (u4 == gmax) ? base + 4 : BIG;
        int i5 = (u5 == gmax) ? base + 5 : BIG;
        int i6 = (u6 == gmax) ? base + 6 : BIG;
        int i7 = (u7 == gmax) ? base + 7 : BIG;
        int idx = min(min(min(i0, i1), min(i2, i3)),
                      min(min(i4, i5), min(i6, i7)));
        cur = __reduce_min_sync(FULL, idx);
        if (lane == 0) out[b * TT + (TT - 1)] = (float)cur;
    }

    // one chain step: state row (t-1) given in (sa, sb); updates cur, writes out
    auto argstep = [&](float4 sa, float4 sb, int t) {
        const float* trow = (cur < SROWS) ? (sT + cur * KK)
                                          : (g_transT + cur * KK);
        float4 t0 = *(const float4*)(trow + base);
        float4 t1 = *(const float4*)(trow + base + 4);
        unsigned u0 = fmono(sa.x + t0.x), u1 = fmono(sa.y + t0.y);
        unsigned u2 = fmono(sa.z + t0.z), u3 = fmono(sa.w + t0.w);
        unsigned u4 = fmono(sb.x + t1.x), u5 = fmono(sb.y + t1.y);
        unsigned u6 = fmono(sb.z + t1.z), u7 = fmono(sb.w + t1.w);
        unsigned um = max(max(max(u0, u1), max(u2, u3)),
                          max(max(u4, u5), max(u6, u7)));
        unsigned gmax = __reduce_max_sync(FULL, um);
        int i0 = (u0 == gmax) ? base + 0 : BIG;
        int i1 = (u1 == gmax) ? base + 1 : BIG;
        int i2 = (u2 == gmax) ? base + 2 : BIG;
        int i3 = (u3 == gmax) ? base + 3 : BIG;
        int i4 = (u4 == gmax) ? base + 4 : BIG;
        int i5 = (u5 == gmax) ? base + 5 : BIG;
        int i6 = (u6 == gmax) ? base + 6 : BIG;
        int i7 = (u7 == gmax) ? base + 7 : BIG;
        int idx = min(min(min(i0, i1), min(i2, i3)),
                      min(min(i4, i5), min(i6, i7)));
        cur = __reduce_min_sync(FULL, idx);
        if (lane == 0) out[b * TT + (t - 1)] = (float)cur;
    };

    // depth-8 register prefetch; slot d holds row (1022 - d) = (t-1) at t=1023-d
    float4 pfa[8], pfb[8];
    #pragma unroll
    for (int d = 0; d < 8; ++d) {
        const float4* rp = (const float4*)(g_state + ((1022 - d) * BB + b) * KK) + lane * 2;
        pfa[d] = __ldg(rp);
        pfb[d] = __ldg(rp + 1);
    }

    int t = 1023;
    while (t >= 8) {                 // full blocks: slots are compile-time
        #pragma unroll
        for (int uu = 0; uu < 8; ++uu) {
            float4 sa = pfa[uu], sb = pfb[uu];
            int nrow = t - 9;        // refill slot uu for use 8 iters from now
            if (nrow >= 0) {
                const float4* rp = (const float4*)(g_state + (nrow * BB + b) * KK) + lane * 2;
                pfa[uu] = __ldg(rp);
                pfb[uu] = __ldg(rp + 1);
            }
            argstep(sa, sb, t);
            --t;
        }
    }
    while (t >= 1) {                 // tail (<=7 iters): direct loads, no arrays
        const float4* rp = (const float4*)(g_state + ((t - 1) * BB + b) * KK) + lane * 2;
        float4 sa = __ldg(rp), sb = __ldg(rp + 1);
        argstep(sa, sb, t);
        --t;
    }
}

// ---------------- launch ----------------------------------------------------
extern "C" void kernel_launch(void* const* d_in, const int* in_sizes, int n_in,
                              void* d_out, int out_size)
{
    const float* em    = (const float*)d_in[0];  // [B, T, K] fp32
    const float* trans = (const float*)d_in[1];  // [K, K] fp32
    float* out = (float*)d_out;                  // [B, T] fp32

    const int bt_smem = SROWS * KK * (int)sizeof(float);   // 229376
    cudaFuncSetAttribute(backtrace_kernel,
                         cudaFuncAttributeMaxDynamicSharedMemorySize, bt_smem);

    transpose_kernel<<<dim3(8, 8), dim3(32, 8)>>>(trans);   // launch 1
    noop_kernel<<<1, 32>>>();                               // launch 2
    noop_kernel<<<1, 32>>>();                               // launch 3
    fwd_kernel<<<2 * BB, 256>>>(em, trans);                 // launch 4 <- ncu
    backtrace_kernel<<<BB, 256, bt_smem>>>(out);            // launch 5
}